// round 1
// baseline (speedup 1.0000x reference)
#include <cuda_runtime.h>
#include <math.h>

#define N_NODES 8192
#define IN_F    256
#define OUT_F   64
#define JSPLIT  8
#define JRANGE  (N_NODES / JSPLIT)   // 1024 j per block
#define JC      128                  // j chunk staged in smem
#define RPB     256                  // rows (=threads) per block
#define PSTRIDE 68                   // padded partial-row stride (floats)

// ---------------- static device scratch (no allocations allowed) -----------
__device__ float  g_h[N_NODES * OUT_F];                     // 2 MB
__device__ float  g_f1[N_NODES], g_E1[N_NODES], g_Q1[N_NODES];
__device__ float4 g_f2p[N_NODES];                           // {f2, exp(f2), exp(.2 f2), 0}
__device__ float  g_part[JSPLIT][N_NODES][PSTRIDE];         // ~17.8 MB partials

// ---------------- kernel 1: h = X@W, f1/f2 + exponentials ------------------
// warp = 4 rows; lane owns cols (lane, lane+32). W (64KB) stays L1-resident.
__global__ void k_h(const float* __restrict__ X, const float* __restrict__ W,
                    const float* __restrict__ a) {
    int warp = threadIdx.x >> 5, lane = threadIdx.x & 31;
    int row0 = (blockIdx.x * 8 + warp) * 4;
    const float* x0 = X + (size_t)row0 * IN_F;

    float acc[8];
    #pragma unroll
    for (int i = 0; i < 8; i++) acc[i] = 0.f;

    for (int k = 0; k < IN_F; k += 4) {
        float4 xv[4];
        #pragma unroll
        for (int r = 0; r < 4; r++)
            xv[r] = *(const float4*)(x0 + (size_t)r * IN_F + k);   // lane-broadcast
        #pragma unroll
        for (int kk = 0; kk < 4; kk++) {
            float w0 = __ldg(W + (k + kk) * OUT_F + lane);
            float w1 = __ldg(W + (k + kk) * OUT_F + 32 + lane);
            #pragma unroll
            for (int r = 0; r < 4; r++) {
                const float* xp = (const float*)&xv[r];
                acc[2*r]   = fmaf(xp[kk], w0, acc[2*r]);
                acc[2*r+1] = fmaf(xp[kk], w1, acc[2*r+1]);
            }
        }
    }

    #pragma unroll
    for (int r = 0; r < 4; r++) {
        int row = row0 + r;
        g_h[(size_t)row * OUT_F + lane]      = acc[2*r];
        g_h[(size_t)row * OUT_F + 32 + lane] = acc[2*r+1];
        float p1 = acc[2*r] * __ldg(a + lane)      + acc[2*r+1] * __ldg(a + 32 + lane);
        float p2 = acc[2*r] * __ldg(a + 64 + lane) + acc[2*r+1] * __ldg(a + 96 + lane);
        #pragma unroll
        for (int o = 16; o > 0; o >>= 1) {
            p1 += __shfl_xor_sync(0xffffffffu, p1, o);
            p2 += __shfl_xor_sync(0xffffffffu, p2, o);
        }
        if (lane == 0) {
            g_f1[row] = p1;
            g_E1[row] = expf(p1);
            g_Q1[row] = expf(0.2f * p1);
            g_f2p[row] = make_float4(p2, expf(p2), expf(0.2f * p2), 0.f);
        }
    }
}

// ---------------- kernel 2: fused masked-softmax numerator/denominator -----
// Each thread owns one row i (64 fp32 accumulators in registers). All lanes
// of a warp walk the same j => h[j] is a conflict-free SMEM broadcast.
// exp(leaky_relu(f1+f2)) = (s>=0) ? E1[i]*E2[j] : Q1[i]*Q2[j]  — no MUFU.
__global__ void __launch_bounds__(RPB, 2)
k_attn(const int* __restrict__ adj) {
    __shared__ float4 s_h[JC * (OUT_F / 4)];   // 32 KB
    __shared__ float4 s_f2[JC];                // 2 KB

    int t   = threadIdx.x;
    int row = blockIdx.x * RPB + t;
    int js  = blockIdx.y;
    int jbase0 = js * JRANGE;

    float f1 = g_f1[row], e1 = g_E1[row], q1 = g_Q1[row];
    float acc[OUT_F];
    #pragma unroll
    for (int d = 0; d < OUT_F; d++) acc[d] = 0.f;
    float den = 0.f;

    const int* adjr = adj + (size_t)row * N_NODES;

    for (int c = 0; c < JRANGE; c += JC) {
        int jb = jbase0 + c;
        // stage h chunk (JC x 64 fp32 = 32KB) + f2 tuples
        const float4* hsrc = (const float4*)(g_h + (size_t)jb * OUT_F);
        #pragma unroll
        for (int u = 0; u < (JC * OUT_F / 4) / RPB; u++)
            s_h[u * RPB + t] = hsrc[u * RPB + t];
        if (t < JC) s_f2[t] = g_f2p[jb + t];
        __syncthreads();

        #pragma unroll 1
        for (int jj = 0; jj < JC; jj += 4) {
            int4 a4 = *(const int4*)(adjr + jb + jj);
            int av[4] = { a4.x, a4.y, a4.z, a4.w };
            #pragma unroll
            for (int r = 0; r < 4; r++) {
                float4 fp = s_f2[jj + r];
                float s = f1 + fp.x;
                float w = (s >= 0.f) ? e1 * fp.y : q1 * fp.z;
                w = (av[r] > 0) ? w : 0.f;
                den += w;
                const float4* hp = s_h + (jj + r) * (OUT_F / 4);
                #pragma unroll
                for (int d4 = 0; d4 < OUT_F / 4; d4++) {
                    float4 hv = hp[d4];
                    acc[d4*4+0] = fmaf(w, hv.x, acc[d4*4+0]);
                    acc[d4*4+1] = fmaf(w, hv.y, acc[d4*4+1]);
                    acc[d4*4+2] = fmaf(w, hv.z, acc[d4*4+2]);
                    acc[d4*4+3] = fmaf(w, hv.w, acc[d4*4+3]);
                }
            }
        }
        __syncthreads();
    }

    float* po = &g_part[js][row][0];   // 16B-aligned (stride 68 floats)
    #pragma unroll
    for (int d4 = 0; d4 < OUT_F / 4; d4++)
        *(float4*)(po + d4 * 4) =
            make_float4(acc[d4*4], acc[d4*4+1], acc[d4*4+2], acc[d4*4+3]);
    po[OUT_F] = den;
}

// ---------------- kernel 3: reduce partials, divide, ELU -------------------
__global__ void k_final(float* __restrict__ out) {
    int row = blockIdx.x;
    int d = threadIdx.x;          // 64 threads
    float num = 0.f, den = 0.f;
    #pragma unroll
    for (int js = 0; js < JSPLIT; js++) {
        num += g_part[js][row][d];
        den += g_part[js][row][OUT_F];
    }
    float v = num / den;
    out[(size_t)row * OUT_F + d] = (v > 0.f) ? v : expm1f(v);
}

// ---------------- launch ----------------------------------------------------
extern "C" void kernel_launch(void* const* d_in, const int* in_sizes, int n_in,
                              void* d_out, int out_size) {
    const float* X = nullptr; const int* adj = nullptr;
    const float* W = nullptr; const float* a = nullptr;
    for (int i = 0; i < n_in; i++) {
        switch (in_sizes[i]) {
            case N_NODES * IN_F:    X   = (const float*)d_in[i]; break;
            case N_NODES * N_NODES: adj = (const int*)  d_in[i]; break;
            case IN_F * OUT_F:      W   = (const float*)d_in[i]; break;
            case 2 * OUT_F:         a   = (const float*)d_in[i]; break;
        }
    }
    k_h<<<N_NODES / 32, 256>>>(X, W, a);
    dim3 g2(N_NODES / RPB, JSPLIT);
    k_attn<<<g2, RPB>>>(adj);
    k_final<<<N_NODES, OUT_F>>>((float*)d_out);
}

// round 2
// speedup vs baseline: 1.0748x; 1.0748x over previous
#include <cuda_runtime.h>
#include <math.h>

#define N_NODES 8192
#define IN_F    256
#define OUT_F   64
#define JSPLIT  8
#define JRANGE  (N_NODES / JSPLIT)   // 1024 j per block
#define JC      128                  // j chunk staged in smem
#define RPB     256                  // rows (=threads) per block
#define PSTRIDE 68                   // padded partial-row stride (floats)

// ---------------- static device scratch (no allocations allowed) -----------
__device__ float  g_h[N_NODES * OUT_F];                     // 2 MB
__device__ float  g_f1[N_NODES], g_E1[N_NODES], g_Q1[N_NODES];
__device__ float4 g_f2p[N_NODES];                           // {f2, exp(f2), exp(.2 f2), 0}
__device__ float  g_part[JSPLIT][N_NODES][PSTRIDE];         // ~17.8 MB partials

// ---------------- kernel 1: h = X@W, f1/f2 + exponentials ------------------
// 1 row per warp, grid 1024 blocks -> deep occupancy to hide LDG latency.
// lane owns cols (lane, lane+32); W stays L1-resident after first block wave.
__global__ void k_h(const float* __restrict__ X, const float* __restrict__ W,
                    const float* __restrict__ a) {
    int warp = threadIdx.x >> 5, lane = threadIdx.x & 31;
    int row  = blockIdx.x * 8 + warp;
    const float* x0 = X + (size_t)row * IN_F;

    float acc0 = 0.f, acc1 = 0.f;

    #pragma unroll 4
    for (int k = 0; k < IN_F; k += 4) {
        float4 xv = *(const float4*)(x0 + k);   // lane-uniform broadcast LDG
        const float* xp = (const float*)&xv;
        #pragma unroll
        for (int kk = 0; kk < 4; kk++) {
            float w0 = __ldg(W + (k + kk) * OUT_F + lane);
            float w1 = __ldg(W + (k + kk) * OUT_F + 32 + lane);
            acc0 = fmaf(xp[kk], w0, acc0);
            acc1 = fmaf(xp[kk], w1, acc1);
        }
    }

    g_h[(size_t)row * OUT_F + lane]      = acc0;
    g_h[(size_t)row * OUT_F + 32 + lane] = acc1;

    float p1 = acc0 * __ldg(a + lane)      + acc1 * __ldg(a + 32 + lane);
    float p2 = acc0 * __ldg(a + 64 + lane) + acc1 * __ldg(a + 96 + lane);
    #pragma unroll
    for (int o = 16; o > 0; o >>= 1) {
        p1 += __shfl_xor_sync(0xffffffffu, p1, o);
        p2 += __shfl_xor_sync(0xffffffffu, p2, o);
    }
    if (lane == 0) {
        g_f1[row] = p1;
        g_E1[row] = expf(p1);
        g_Q1[row] = expf(0.2f * p1);
        g_f2p[row] = make_float4(p2, expf(p2), expf(0.2f * p2), 0.f);
    }
}

// ---------------- kernel 2: fused masked-softmax numerator/denominator -----
// Thread owns row i; 64 fp32 accumulators held as 32 packed f32x2 (b64).
// All lanes of a warp walk the same j => h[j] is conflict-free SMEM broadcast.
// exp(leaky_relu(f1+f2)) = (s>=0) ? E1[i]*E2[j] : Q1[i]*Q2[j]  — zero MUFU.
// Inner product uses Blackwell packed fma.rn.f32x2: 32 FMA-inst/j vs 64.
__global__ void __launch_bounds__(RPB, 2)
k_attn(const int* __restrict__ adj) {
    __shared__ float4 s_h[JC * (OUT_F / 4)];   // 32 KB
    __shared__ float4 s_f2[JC];                // 2 KB

    int t   = threadIdx.x;
    int row = blockIdx.x * RPB + t;
    int js  = blockIdx.y;
    int jbase0 = js * JRANGE;

    float f1 = g_f1[row], e1 = g_E1[row], q1 = g_Q1[row];

    unsigned long long acc[OUT_F / 2];         // 32 packed f32x2 accumulators
    #pragma unroll
    for (int d = 0; d < OUT_F / 2; d++) acc[d] = 0ull;
    float den = 0.f;

    const int* adjr = adj + (size_t)row * N_NODES;

    for (int c = 0; c < JRANGE; c += JC) {
        int jb = jbase0 + c;
        const float4* hsrc = (const float4*)(g_h + (size_t)jb * OUT_F);
        #pragma unroll
        for (int u = 0; u < (JC * OUT_F / 4) / RPB; u++)
            s_h[u * RPB + t] = hsrc[u * RPB + t];
        if (t < JC) s_f2[t] = g_f2p[jb + t];
        __syncthreads();

        #pragma unroll 1
        for (int jj = 0; jj < JC; jj += 4) {
            int4 a4 = *(const int4*)(adjr + jb + jj);
            int av[4] = { a4.x, a4.y, a4.z, a4.w };
            #pragma unroll
            for (int r = 0; r < 4; r++) {
                float4 fp = s_f2[jj + r];
                float s = f1 + fp.x;
                float w = (s >= 0.f) ? e1 * fp.y : q1 * fp.z;
                w = (av[r] != 0) ? w : 0.f;
                den += w;
                unsigned long long wp;
                asm("mov.b64 %0, {%1, %1};" : "=l"(wp) : "f"(w));
                const ulonglong2* hp =
                    (const ulonglong2*)(s_h + (jj + r) * (OUT_F / 4));
                #pragma unroll
                for (int d = 0; d < OUT_F / 4; d++) {   // 16 LDS.128 -> 32 b64
                    ulonglong2 hv = hp[d];
                    asm("fma.rn.f32x2 %0, %1, %2, %0;"
                        : "+l"(acc[2*d])   : "l"(wp), "l"(hv.x));
                    asm("fma.rn.f32x2 %0, %1, %2, %0;"
                        : "+l"(acc[2*d+1]) : "l"(wp), "l"(hv.y));
                }
            }
        }
        __syncthreads();
    }

    float* po = &g_part[js][row][0];   // base 16B-aligned, stride 272B (16|272)
    #pragma unroll
    for (int d = 0; d < OUT_F / 4; d++) {
        ulonglong2 v; v.x = acc[2*d]; v.y = acc[2*d+1];
        *(ulonglong2*)(po + d * 4) = v;
    }
    po[OUT_F] = den;
}

// ---------------- kernel 3: reduce partials, divide, ELU -------------------
__global__ void k_final(float* __restrict__ out) {
    int row = blockIdx.x;
    int d = threadIdx.x;          // 64 threads
    float num = 0.f, den = 0.f;
    #pragma unroll
    for (int js = 0; js < JSPLIT; js++) {
        num += g_part[js][row][d];
        den += g_part[js][row][OUT_F];
    }
    float v = num / den;
    out[(size_t)row * OUT_F + d] = (v > 0.f) ? v : expm1f(v);
}

// ---------------- launch ----------------------------------------------------
extern "C" void kernel_launch(void* const* d_in, const int* in_sizes, int n_in,
                              void* d_out, int out_size) {
    const float* X = nullptr; const int* adj = nullptr;
    const float* W = nullptr; const float* a = nullptr;
    for (int i = 0; i < n_in; i++) {
        switch (in_sizes[i]) {
            case N_NODES * IN_F:    X   = (const float*)d_in[i]; break;
            case N_NODES * N_NODES: adj = (const int*)  d_in[i]; break;
            case IN_F * OUT_F:      W   = (const float*)d_in[i]; break;
            case 2 * OUT_F:         a   = (const float*)d_in[i]; break;
        }
    }
    k_h<<<N_NODES / 8, 256>>>(X, W, a);
    dim3 g2(N_NODES / RPB, JSPLIT);
    k_attn<<<g2, RPB>>>(adj);
    k_final<<<N_NODES, OUT_F>>>((float*)d_out);
}

// round 3
// speedup vs baseline: 1.2012x; 1.1176x over previous
#include <cuda_runtime.h>
#include <math.h>

#define N_NODES 8192
#define IN_F    256
#define OUT_F   64
#define JSPLIT  8
#define JRANGE  (N_NODES / JSPLIT)   // 1024 j per (row-block, js)
#define JC      128                  // j chunk staged in smem
#define RPB     256                  // rows (=threads) per block
#define PSTRIDE 68                   // padded partial-row stride (floats)

// ---------------- static device scratch (no allocations allowed) -----------
__device__ float  g_h[N_NODES * OUT_F];                     // 2 MB
__device__ float  g_f1[N_NODES], g_E1[N_NODES], g_Q1[N_NODES];
__device__ float4 g_f2p[N_NODES];                           // {f2, exp(f2), exp(.2f2), 0}
__device__ float  g_part[JSPLIT][N_NODES][PSTRIDE];         // ~17.8 MB partials

// ---------------- kernel 1: h = X@W, f1/f2 + exponentials ------------------
// 2 rows per warp for ILP on the LDG->FFMA chains; W stays L1-resident.
__global__ void k_h(const float* __restrict__ X, const float* __restrict__ W,
                    const float* __restrict__ a) {
    int warp = threadIdx.x >> 5, lane = threadIdx.x & 31;
    int row0 = (blockIdx.x * 8 + warp) * 2;
    const float* x0 = X + (size_t)row0 * IN_F;

    float a00 = 0.f, a01 = 0.f, a10 = 0.f, a11 = 0.f;

    #pragma unroll 2
    for (int k = 0; k < IN_F; k += 4) {
        float4 xa = *(const float4*)(x0 + k);            // row0, lane-broadcast
        float4 xb = *(const float4*)(x0 + IN_F + k);     // row0+1
        const float* pa = (const float*)&xa;
        const float* pb = (const float*)&xb;
        #pragma unroll
        for (int kk = 0; kk < 4; kk++) {
            float w0 = __ldg(W + (k + kk) * OUT_F + lane);
            float w1 = __ldg(W + (k + kk) * OUT_F + 32 + lane);
            a00 = fmaf(pa[kk], w0, a00);
            a01 = fmaf(pa[kk], w1, a01);
            a10 = fmaf(pb[kk], w0, a10);
            a11 = fmaf(pb[kk], w1, a11);
        }
    }

    float accs[2][2] = {{a00, a01}, {a10, a11}};
    #pragma unroll
    for (int r = 0; r < 2; r++) {
        int row = row0 + r;
        g_h[(size_t)row * OUT_F + lane]      = accs[r][0];
        g_h[(size_t)row * OUT_F + 32 + lane] = accs[r][1];
        float p1 = accs[r][0] * __ldg(a + lane)      + accs[r][1] * __ldg(a + 32 + lane);
        float p2 = accs[r][0] * __ldg(a + 64 + lane) + accs[r][1] * __ldg(a + 96 + lane);
        #pragma unroll
        for (int o = 16; o > 0; o >>= 1) {
            p1 += __shfl_xor_sync(0xffffffffu, p1, o);
            p2 += __shfl_xor_sync(0xffffffffu, p2, o);
        }
        if (lane == 0) {
            g_f1[row] = p1;
            g_E1[row] = expf(p1);
            g_Q1[row] = expf(0.2f * p1);
            g_f2p[row] = make_float4(p2, expf(p2), expf(0.2f * p2), 0.f);
        }
    }
}

// ---------------- kernel 2: fused masked-softmax num/den --------------------
// Thread owns row i (32 packed f32x2 accumulators). Lanes of a warp walk the
// same j => h[j]/f2[j] are conflict-free SMEM broadcasts.
// adj is COMPRESSED TO BITS per chunk: each warp loads one adj row coalesced
// (lanes read consecutive int4 = 512B contiguous), ballot -> 4 x 32-bit masks.
// Consumer reads one uint4 (16B) of bits per 128 j. This removes the 32-line
// per-LDG sector storm that bound R1/R2.
// Bit layout: word k (k=0..3), bit p  <->  j = chunk_base + p*4 + k.
__global__ void __launch_bounds__(RPB, 2)
k_attn(const int* __restrict__ adj) {
    __shared__ float4 s_h[JC * (OUT_F / 4)];   // 32 KB
    __shared__ float4 s_f2[JC];                // 2 KB
    __shared__ uint4  s_bits[RPB];             // 4 KB

    int t    = threadIdx.x;
    int lane = t & 31, wp = t >> 5;
    int row  = blockIdx.x * RPB + t;
    int js   = blockIdx.y;
    int jbase0 = js * JRANGE;

    float f1 = g_f1[row], e1 = g_E1[row], q1 = g_Q1[row];

    unsigned long long acc[OUT_F / 2];         // 32 packed f32x2 accumulators
    #pragma unroll
    for (int d = 0; d < OUT_F / 2; d++) acc[d] = 0ull;
    float den0 = 0.f, den1 = 0.f, den2 = 0.f, den3 = 0.f;

    int prow0 = blockIdx.x * RPB + wp * 32;    // producer: this warp's 32 rows

    for (int c = 0; c < JRANGE; c += JC) {
        int jb = jbase0 + c;

        // ---- stage h chunk + f2 tuples ----
        const float4* hsrc = (const float4*)(g_h + (size_t)jb * OUT_F);
        #pragma unroll
        for (int u = 0; u < (JC * OUT_F / 4) / RPB; u++)
            s_h[u * RPB + t] = hsrc[u * RPB + t];
        if (t < JC) s_f2[t] = g_f2p[jb + t];

        // ---- stage adj bits: warp-per-row, coalesced 512B reads ----
        #pragma unroll 4
        for (int rr = 0; rr < 32; rr++) {
            const int4 v = *(const int4*)(adj + (size_t)(prow0 + rr) * N_NODES
                                          + jb + lane * 4);
            unsigned b0 = __ballot_sync(0xffffffffu, v.x != 0);
            unsigned b1 = __ballot_sync(0xffffffffu, v.y != 0);
            unsigned b2 = __ballot_sync(0xffffffffu, v.z != 0);
            unsigned b3 = __ballot_sync(0xffffffffu, v.w != 0);
            if (lane == 0) s_bits[wp * 32 + rr] = make_uint4(b0, b1, b2, b3);
        }
        __syncthreads();

        uint4 bw = s_bits[t];   // this row's 128 adjacency bits for the chunk

        #pragma unroll 1
        for (int jj = 0; jj < JC; jj += 4) {
            unsigned m0 = bw.x & 1u, m1 = bw.y & 1u, m2 = bw.z & 1u, m3 = bw.w & 1u;
            bw.x >>= 1; bw.y >>= 1; bw.z >>= 1; bw.w >>= 1;
            unsigned mv[4] = { m0, m1, m2, m3 };
            #pragma unroll
            for (int r = 0; r < 4; r++) {
                float4 fp = s_f2[jj + r];
                float s = f1 + fp.x;
                float w = (s >= 0.f) ? e1 * fp.y : q1 * fp.z;
                w = mv[r] ? w : 0.f;
                if (r == 0) den0 += w; else if (r == 1) den1 += w;
                else if (r == 2) den2 += w; else den3 += w;
                unsigned long long wpk;
                asm("mov.b64 %0, {%1, %1};" : "=l"(wpk) : "f"(w));
                const ulonglong2* hp =
                    (const ulonglong2*)(s_h + (jj + r) * (OUT_F / 4));
                #pragma unroll
                for (int d = 0; d < OUT_F / 4; d++) {
                    ulonglong2 hv = hp[d];
                    asm("fma.rn.f32x2 %0, %1, %2, %0;"
                        : "+l"(acc[2*d])   : "l"(wpk), "l"(hv.x));
                    asm("fma.rn.f32x2 %0, %1, %2, %0;"
                        : "+l"(acc[2*d+1]) : "l"(wpk), "l"(hv.y));
                }
            }
        }
        __syncthreads();
    }

    float* po = &g_part[js][row][0];
    #pragma unroll
    for (int d = 0; d < OUT_F / 4; d++) {
        ulonglong2 v; v.x = acc[2*d]; v.y = acc[2*d+1];
        *(ulonglong2*)(po + d * 4) = v;
    }
    po[OUT_F] = (den0 + den1) + (den2 + den3);
}

// ---------------- kernel 3: reduce partials, divide, ELU -------------------
__global__ void k_final(float* __restrict__ out) {
    int row = blockIdx.x;
    int d = threadIdx.x;          // 64 threads
    float num = 0.f, den = 0.f;
    #pragma unroll
    for (int js = 0; js < JSPLIT; js++) {
        num += g_part[js][row][d];
        den += g_part[js][row][OUT_F];
    }
    float v = num / den;
    out[(size_t)row * OUT_F + d] = (v > 0.f) ? v : expm1f(v);
}

// ---------------- launch ----------------------------------------------------
extern "C" void kernel_launch(void* const* d_in, const int* in_sizes, int n_in,
                              void* d_out, int out_size) {
    const float* X = nullptr; const int* adj = nullptr;
    const float* W = nullptr; const float* a = nullptr;
    for (int i = 0; i < n_in; i++) {
        switch (in_sizes[i]) {
            case N_NODES * IN_F:    X   = (const float*)d_in[i]; break;
            case N_NODES * N_NODES: adj = (const int*)  d_in[i]; break;
            case IN_F * OUT_F:      W   = (const float*)d_in[i]; break;
            case 2 * OUT_F:         a   = (const float*)d_in[i]; break;
        }
    }
    k_h<<<N_NODES / 16, 256>>>(X, W, a);
    dim3 g2(N_NODES / RPB, JSPLIT);
    k_attn<<<g2, RPB>>>(adj);
    k_final<<<N_NODES, OUT_F>>>((float*)d_out);
}

// round 5
// speedup vs baseline: 2.1077x; 1.7547x over previous
#include <cuda_runtime.h>
#include <math.h>
#include <stdint.h>

#define N_NODES 8192
#define IN_F    256
#define OUT_F   64
#define QSPLIT  4
#define KQ      (N_NODES / QSPLIT)     // 2048 j per CTA
#define CH      32                     // j per chunk (4 ksteps of 8)
#define NCH     (KQ / CH)              // 64 chunks
#define MT      128                    // rows per CTA (8 warps x 16)
#define PS      132
#define BSLOTS  1152                   // 4 ksteps * 9 nblk * 32 lanes (float4)
#define BBYTES  (BSLOTS * 16)          // 18432 B per chunk
#define FONE    0x3F800000u

// ---------------- static device scratch ------------------------------------
__device__ float  g_f1[N_NODES], g_E1[N_NODES], g_Q1[N_NODES], g_f2v[N_NODES];
// fragment-ordered B: [jstep][nblk(8)+den(1)][lane] = {he0,he1,hq0,hq1}
__device__ float4 g_Bpack[N_NODES / 8][9][32];            // 4.7 MB
__device__ float  g_pD[QSPLIT][N_NODES][PS];              // partials

// ---------------- helpers ----------------------------------------------------
__device__ __forceinline__ float to_tf32(float x) {
    uint32_t u; asm("cvt.rna.tf32.f32 %0, %1;" : "=r"(u) : "f"(x));
    return __uint_as_float(u);
}
__device__ __forceinline__ uint32_t smem_u32(const void* p) {
    uint32_t a;
    asm("{ .reg .u64 t; cvta.to.shared.u64 t, %1; cvt.u32.u64 %0, t; }"
        : "=r"(a) : "l"(p));
    return a;
}
__device__ __forceinline__ void mma8(float* d, uint32_t a0, uint32_t a1,
                                     uint32_t a2, uint32_t a3,
                                     uint32_t b0, uint32_t b1) {
    asm volatile(
        "mma.sync.aligned.m16n8k8.row.col.f32.tf32.tf32.f32 "
        "{%0,%1,%2,%3}, {%4,%5,%6,%7}, {%8,%9}, {%0,%1,%2,%3};"
        : "+f"(d[0]), "+f"(d[1]), "+f"(d[2]), "+f"(d[3])
        : "r"(a0), "r"(a1), "r"(a2), "r"(a3), "r"(b0), "r"(b1));
}
#define BITF(w, sh) (((((w) >> (sh)) & 1u)) ? FONE : 0u)
#define CP16(sdst, gsrc) \
    asm volatile("cp.async.cg.shared.global [%0], [%1], 16;" \
                 :: "r"(sdst), "l"(gsrc) : "memory")
#define CP_COMMIT() asm volatile("cp.async.commit_group;" ::: "memory")
#define CP_WAIT1()  asm volatile("cp.async.wait_group 1;" ::: "memory")
#define CP_WAIT0()  asm volatile("cp.async.wait_group 0;" ::: "memory")

// ---------------- kernel 1: h = X@W, scalars + fragment-packed B -----------
__global__ void k_h(const float* __restrict__ X, const float* __restrict__ W,
                    const float* __restrict__ a) {
    int warp = threadIdx.x >> 5, lane = threadIdx.x & 31;
    int row0 = (blockIdx.x * 8 + warp) * 2;
    const float* x0 = X + (size_t)row0 * IN_F;

    float a00 = 0.f, a01 = 0.f, a10 = 0.f, a11 = 0.f;
    #pragma unroll 2
    for (int k = 0; k < IN_F; k += 4) {
        float4 xa = *(const float4*)(x0 + k);
        float4 xb = *(const float4*)(x0 + IN_F + k);
        const float* pa = (const float*)&xa;
        const float* pb = (const float*)&xb;
        #pragma unroll
        for (int kk = 0; kk < 4; kk++) {
            float w0 = __ldg(W + (k + kk) * OUT_F + lane);
            float w1 = __ldg(W + (k + kk) * OUT_F + 32 + lane);
            a00 = fmaf(pa[kk], w0, a00);  a01 = fmaf(pa[kk], w1, a01);
            a10 = fmaf(pb[kk], w0, a10);  a11 = fmaf(pb[kk], w1, a11);
        }
    }

    float accs[2][2] = {{a00, a01}, {a10, a11}};
    #pragma unroll
    for (int r = 0; r < 2; r++) {
        int row = row0 + r;
        float c0 = accs[r][0], c1 = accs[r][1];
        float p1 = c0 * __ldg(a + lane)      + c1 * __ldg(a + 32 + lane);
        float p2 = c0 * __ldg(a + 64 + lane) + c1 * __ldg(a + 96 + lane);
        #pragma unroll
        for (int o = 16; o > 0; o >>= 1) {
            p1 += __shfl_xor_sync(0xffffffffu, p1, o);
            p2 += __shfl_xor_sync(0xffffffffu, p2, o);
        }
        float e2 = expf(p2), q2 = expf(0.2f * p2);
        int s = row >> 3, cp = row & 3, half = (row >> 2) & 1;

        // he/hq fragment slots for d = lane and d = lane+32
        {
            int d = lane;
            float* bb = (float*)&g_Bpack[s][d >> 3][((d & 7) << 2) | cp];
            bb[half]     = to_tf32(c0 * e2);
            bb[2 + half] = to_tf32(c0 * q2);
        }
        {
            int d = lane + 32;
            float* bb = (float*)&g_Bpack[s][d >> 3][((d & 7) << 2) | cp];
            bb[half]     = to_tf32(c1 * e2);
            bb[2 + half] = to_tf32(c1 * q2);
        }
        // den slot (nblk 8): value depends only on j; lanes with matching c write
        if ((lane & 3) == cp) {
            float* bd = (float*)&g_Bpack[s][8][lane];
            bd[half]     = to_tf32(e2);
            bd[2 + half] = to_tf32(q2);
        }
        if (lane == 0) {
            g_f1[row]  = p1;
            g_E1[row]  = expf(p1);
            g_Q1[row]  = expf(0.2f * p1);
            g_f2v[row] = p2;
        }
    }
}

// ---------------- kernel 2: binary-mask tf32 mma.sync GEMM ------------------
// Warp: 16 rows x (64 cols + den) x K=2048, two GEMMs (P@he, N@hq).
// A = 0/1 masks built in registers from coalesced adj ballots (sign test
// folded in). B staged per 32-j chunk via double-buffered cp.async from
// fragment-ordered g_Bpack; one LDS.128 feeds both GEMMs' B fragments.
__global__ void __launch_bounds__(256, 2)
k_attn(const int* __restrict__ adj) {
    __shared__ float4 smB[2][BSLOTS];   // 36 KB
    __shared__ float  s_f1[MT];

    int t = threadIdx.x, lane = t & 31, wid = t >> 5;
    int g = lane >> 2, c = lane & 3;
    int strip = blockIdx.x * MT;
    int q = blockIdx.y, jq = q * KQ;

    if (t < MT) s_f1[t] = g_f1[strip + t];

    float aP[9][4], aN[9][4];
    #pragma unroll
    for (int b = 0; b < 9; b++)
        #pragma unroll
        for (int v = 0; v < 4; v++) { aP[b][v] = 0.f; aN[b][v] = 0.f; }

    uint32_t smb = smem_u32(&smB[0][0]);
    const char* bsrc = (const char*)&g_Bpack[jq >> 3][0][0];

    // preload chunk 0
    for (int i = t; i < BSLOTS; i += 256)
        CP16(smb + i * 16, bsrc + (size_t)i * 16);
    CP_COMMIT();
    __syncthreads();    // covers s_f1 too

    const int* ap0 = adj + (size_t)(strip + wid * 16) * N_NODES + jq + lane;

    for (int ch = 0; ch < NCH; ch++) {
        int buf = ch & 1;
        if (ch + 1 < NCH) {
            uint32_t d0 = smb + (buf ^ 1) * BBYTES;
            const char* s0 = bsrc + (size_t)(ch + 1) * BBYTES;
            for (int i = t; i < BSLOTS; i += 256)
                CP16(d0 + i * 16, s0 + (size_t)i * 16);
            CP_COMMIT();
        }

        // ---- producer: adj ballots for this warp's 16 rows (coalesced) ----
        float f2l = g_f2v[jq + ch * CH + lane];
        const int* ap = ap0 + ch * CH;
        unsigned P0 = 0, N0 = 0, P1 = 0, N1 = 0;   // rows g and g+8
        #pragma unroll
        for (int rr = 0; rr < 16; rr++) {
            int av = ap[(size_t)rr * N_NODES];
            float f1r = s_f1[wid * 16 + rr];
            bool nz  = (av != 0);
            bool pos = (f1r + f2l) >= 0.f;
            unsigned Pm = __ballot_sync(0xffffffffu, nz && pos);
            unsigned Nm = __ballot_sync(0xffffffffu, nz && !pos);
            if (rr == g)     { P0 = Pm; N0 = Nm; }
            if (rr == g + 8) { P1 = Pm; N1 = Nm; }
        }
        P0 >>= c; N0 >>= c; P1 >>= c; N1 >>= c;

        if (ch + 1 < NCH) CP_WAIT1(); else CP_WAIT0();
        __syncthreads();   // whole B tile visible

        const float4* bbase = &smB[buf][lane];
        #pragma unroll
        for (int s = 0; s < 4; s++) {
            unsigned sh = 8 * s;
            uint32_t pa0 = BITF(P0, sh),     pa1 = BITF(P1, sh);
            uint32_t pa2 = BITF(P0, sh + 4), pa3 = BITF(P1, sh + 4);
            uint32_t na0 = BITF(N0, sh),     na1 = BITF(N1, sh);
            uint32_t na2 = BITF(N0, sh + 4), na3 = BITF(N1, sh + 4);
            const float4* bp = bbase + s * 9 * 32;
            #pragma unroll
            for (int b = 0; b < 9; b++) {
                float4 f = bp[b * 32];
                uint32_t be0 = __float_as_uint(f.x), be1 = __float_as_uint(f.y);
                uint32_t bq0 = __float_as_uint(f.z), bq1 = __float_as_uint(f.w);
                if (b == 8 && g != 0) { be0 = be1 = bq0 = bq1 = 0u; }
                mma8(aP[b], pa0, pa1, pa2, pa3, be0, be1);
                mma8(aN[b], na0, na1, na2, na3, bq0, bq1);
            }
        }
        __syncthreads();   // done reading buf before it is re-filled
    }

    // ---- epilogue: store fragments to partials ----
    int r0 = strip + wid * 16 + g, r1 = r0 + 8;
    float* p0 = &g_pD[q][r0][0];
    float* p1 = &g_pD[q][r1][0];
    #pragma unroll
    for (int b = 0; b < 8; b++) {
        int col = 8 * b + 2 * c;
        *(float2*)(p0 + col)      = make_float2(aP[b][0], aP[b][1]);
        *(float2*)(p1 + col)      = make_float2(aP[b][2], aP[b][3]);
        *(float2*)(p0 + 64 + col) = make_float2(aN[b][0], aN[b][1]);
        *(float2*)(p1 + 64 + col) = make_float2(aN[b][2], aN[b][3]);
    }
    if (c == 0) {   // den lives in column 0 of nblk 8
        p0[128] = aP[8][0];  p0[129] = aN[8][0];
        p1[128] = aP[8][2];  p1[129] = aN[8][2];
    }
}

// ---------------- kernel 3: combine quarters, divide, ELU ------------------
__global__ void k_final(float* __restrict__ out) {
    int row = blockIdx.x;
    int d = threadIdx.x;                 // 64 threads
    float e1 = g_E1[row], q1 = g_Q1[row];
    float n1 = 0.f, n2 = 0.f, de = 0.f, dq = 0.f;
    #pragma unroll
    for (int q = 0; q < QSPLIT; q++) {
        n1 += g_pD[q][row][d];
        n2 += g_pD[q][row][64 + d];
        de += g_pD[q][row][128];
        dq += g_pD[q][row][129];
    }
    float num = e1 * n1 + q1 * n2;
    float den = e1 * de + q1 * dq;
    float v = num / den;
    out[(size_t)row * OUT_F + d] = (v > 0.f) ? v : expm1f(v);
}

// ---------------- launch ----------------------------------------------------
extern "C" void kernel_launch(void* const* d_in, const int* in_sizes, int n_in,
                              void* d_out, int out_size) {
    const float* X = nullptr; const int* adj = nullptr;
    const float* W = nullptr; const float* a = nullptr;
    for (int i = 0; i < n_in; i++) {
        switch (in_sizes[i]) {
            case N_NODES * IN_F:    X   = (const float*)d_in[i]; break;
            case N_NODES * N_NODES: adj = (const int*)  d_in[i]; break;
            case IN_F * OUT_F:      W   = (const float*)d_in[i]; break;
            case 2 * OUT_F:         a   = (const float*)d_in[i]; break;
        }
    }
    k_h<<<N_NODES / 16, 256>>>(X, W, a);
    dim3 g2(N_NODES / MT, QSPLIT);
    k_attn<<<g2, 256>>>(adj);
    k_final<<<N_NODES, OUT_F>>>((float*)d_out);
}

// round 6
// speedup vs baseline: 2.3555x; 1.1176x over previous
#include <cuda_runtime.h>
#include <math.h>
#include <stdint.h>

#define N_NODES 8192
#define IN_F    256
#define OUT_F   64
#define QSPLIT  4
#define KQ      (N_NODES / QSPLIT)     // 2048 j per CTA
#define CH      32                     // j per chunk (4 ksteps of 8)
#define NCH     (KQ / CH)              // 64 chunks
#define MT      128                    // rows per CTA (8 warps x 16)
#define PS      132
#define BSLOTS  1152                   // 4 ksteps * 9 nblk * 32 lanes (float4)
#define BBYTES  (BSLOTS * 16)          // 18432 B per chunk stage
#define NSTG    4                      // cp.async ring stages
#define SMEM_K2 (NSTG * BBYTES + 512)  // 74240 B dynamic smem
#define FONE    0x3F800000u

// ---------------- static device scratch ------------------------------------
__device__ float  g_f1[N_NODES], g_E1[N_NODES], g_Q1[N_NODES], g_f2v[N_NODES];
// fragment-ordered B: [jstep][nblk(8)+den(1)][lane] = {he0,he1,hq0,hq1}
__device__ float4 g_Bpack[N_NODES / 8][9][32];            // 4.7 MB
__device__ float  g_pD[QSPLIT][N_NODES][PS];              // partials

// ---------------- helpers ----------------------------------------------------
__device__ __forceinline__ float to_tf32(float x) {
    uint32_t u; asm("cvt.rna.tf32.f32 %0, %1;" : "=r"(u) : "f"(x));
    return __uint_as_float(u);
}
__device__ __forceinline__ uint32_t smem_u32(const void* p) {
    uint32_t a;
    asm("{ .reg .u64 t; cvta.to.shared.u64 t, %1; cvt.u32.u64 %0, t; }"
        : "=r"(a) : "l"(p));
    return a;
}
__device__ __forceinline__ void mma8(float* d, uint32_t a0, uint32_t a1,
                                     uint32_t a2, uint32_t a3,
                                     uint32_t b0, uint32_t b1) {
    asm volatile(
        "mma.sync.aligned.m16n8k8.row.col.f32.tf32.tf32.f32 "
        "{%0,%1,%2,%3}, {%4,%5,%6,%7}, {%8,%9}, {%0,%1,%2,%3};"
        : "+f"(d[0]), "+f"(d[1]), "+f"(d[2]), "+f"(d[3])
        : "r"(a0), "r"(a1), "r"(a2), "r"(a3), "r"(b0), "r"(b1));
}
#define BITF(w, sh) (((((w) >> (sh)) & 1u)) ? FONE : 0u)
#define CP16(sdst, gsrc) \
    asm volatile("cp.async.cg.shared.global [%0], [%1], 16;" \
                 :: "r"(sdst), "l"(gsrc) : "memory")
#define CP_COMMIT() asm volatile("cp.async.commit_group;" ::: "memory")
#define CP_WAIT2()  asm volatile("cp.async.wait_group 2;" ::: "memory")

// ---------------- kernel 1: h = X@W, scalars + fragment-packed B -----------
// 1 row per warp, grid 1024 -> ~84% occupancy to hide the LDG->FFMA chains.
__global__ void k_h(const float* __restrict__ X, const float* __restrict__ W,
                    const float* __restrict__ a) {
    int warp = threadIdx.x >> 5, lane = threadIdx.x & 31;
    int row  = blockIdx.x * 8 + warp;
    const float* x0 = X + (size_t)row * IN_F;

    float acc0 = 0.f, acc1 = 0.f;
    #pragma unroll 4
    for (int k = 0; k < IN_F; k += 4) {
        float4 xv = *(const float4*)(x0 + k);     // lane-uniform broadcast
        const float* xp = (const float*)&xv;
        #pragma unroll
        for (int kk = 0; kk < 4; kk++) {
            float w0 = __ldg(W + (k + kk) * OUT_F + lane);
            float w1 = __ldg(W + (k + kk) * OUT_F + 32 + lane);
            acc0 = fmaf(xp[kk], w0, acc0);
            acc1 = fmaf(xp[kk], w1, acc1);
        }
    }

    float p1 = acc0 * __ldg(a + lane)      + acc1 * __ldg(a + 32 + lane);
    float p2 = acc0 * __ldg(a + 64 + lane) + acc1 * __ldg(a + 96 + lane);
    #pragma unroll
    for (int o = 16; o > 0; o >>= 1) {
        p1 += __shfl_xor_sync(0xffffffffu, p1, o);
        p2 += __shfl_xor_sync(0xffffffffu, p2, o);
    }
    float e2 = expf(p2), q2 = expf(0.2f * p2);
    int s = row >> 3, cp = row & 3, half = (row >> 2) & 1;

    {   // he/hq fragment slot for d = lane
        float* bb = (float*)&g_Bpack[s][lane >> 3][((lane & 7) << 2) | cp];
        bb[half]     = to_tf32(acc0 * e2);
        bb[2 + half] = to_tf32(acc0 * q2);
    }
    {   // d = lane + 32
        int d = lane + 32;
        float* bb = (float*)&g_Bpack[s][d >> 3][((d & 7) << 2) | cp];
        bb[half]     = to_tf32(acc1 * e2);
        bb[2 + half] = to_tf32(acc1 * q2);
    }
    if ((lane & 3) == cp) {   // den slot (nblk 8)
        float* bd = (float*)&g_Bpack[s][8][lane];
        bd[half]     = to_tf32(e2);
        bd[2 + half] = to_tf32(q2);
    }
    if (lane == 0) {
        g_f1[row]  = p1;
        g_E1[row]  = expf(p1);
        g_Q1[row]  = expf(0.2f * p1);
        g_f2v[row] = p2;
    }
}

// ---------------- kernel 2: binary-mask tf32 mma.sync GEMM ------------------
// Warp: 16 rows x (64 cols + den) x K=2048, two GEMMs (P@he, N@hq).
// A = 0/1 masks built in registers from coalesced adj ballots (sign test
// folded in). B staged via 4-stage cp.async ring from fragment-ordered
// g_Bpack; ONE __syncthreads per chunk (prefetch distance 2: writer stage
// (ch+2)&3 cannot collide with readers at ch&3 or laggards at (ch-1)&3).
__global__ void __launch_bounds__(256, 2)
k_attn(const int* __restrict__ adj) {
    extern __shared__ char dsm[];
    float4* smB = (float4*)dsm;                  // NSTG stages, contiguous
    float*  s_f1 = (float*)(dsm + NSTG * BBYTES);

    int t = threadIdx.x, lane = t & 31, wid = t >> 5;
    int g = lane >> 2, c = lane & 3;
    int strip = blockIdx.x * MT;
    int q = blockIdx.y, jq = q * KQ;

    uint32_t smb = smem_u32(dsm);
    const char* bsrc = (const char*)&g_Bpack[jq >> 3][0][0];

    // prologue: prefetch chunks 0 and 1
    #pragma unroll
    for (int pc = 0; pc < 2; pc++) {
        uint32_t d0 = smb + pc * BBYTES;
        const char* s0 = bsrc + (size_t)pc * BBYTES;
        for (int i = t; i < BSLOTS; i += 256)
            CP16(d0 + i * 16, s0 + (size_t)i * 16);
        CP_COMMIT();
    }
    if (t < MT) s_f1[t] = g_f1[strip + t];
    __syncthreads();                              // s_f1 visible

    float aP[9][4], aN[9][4];
    #pragma unroll
    for (int b = 0; b < 9; b++)
        #pragma unroll
        for (int v = 0; v < 4; v++) { aP[b][v] = 0.f; aN[b][v] = 0.f; }

    const int* ap0 = adj + (size_t)(strip + wid * 16) * N_NODES + jq + lane;

    for (int ch = 0; ch < NCH; ch++) {
        int stg = ch & (NSTG - 1);

        // (a) prefetch ch+2 into stage (ch+2)&3; ALWAYS commit (group counting)
        if (ch + 2 < NCH) {
            uint32_t d0 = smb + ((ch + 2) & (NSTG - 1)) * BBYTES;
            const char* s0 = bsrc + (size_t)(ch + 2) * BBYTES;
            for (int i = t; i < BSLOTS; i += 256)
                CP16(d0 + i * 16, s0 + (size_t)i * 16);
        }
        CP_COMMIT();

        // (b) producer: adj ballots for this warp's 16 rows (coalesced)
        float f2l = g_f2v[jq + ch * CH + lane];
        const int* ap = ap0 + ch * CH;
        unsigned P0 = 0, N0 = 0, P1 = 0, N1 = 0;   // rows g and g+8
        #pragma unroll
        for (int rr = 0; rr < 16; rr++) {
            int av = ap[(size_t)rr * N_NODES];
            float f1r = s_f1[wid * 16 + rr];
            bool nz  = (av != 0);
            bool pos = (f1r + f2l) >= 0.f;
            unsigned Pm = __ballot_sync(0xffffffffu, nz && pos);
            unsigned Nm = __ballot_sync(0xffffffffu, nz && !pos);
            if (rr == g)     { P0 = Pm; N0 = Nm; }
            if (rr == g + 8) { P1 = Pm; N1 = Nm; }
        }
        P0 >>= c; N0 >>= c; P1 >>= c; N1 >>= c;

        // (c)(d) chunk ch resident + visible to all warps
        CP_WAIT2();
        __syncthreads();

        // (e) MMA on stage stg
        const float4* bbase = smB + stg * BSLOTS + lane;
        #pragma unroll
        for (int s = 0; s < 4; s++) {
            unsigned sh = 8 * s;
            uint32_t pa0 = BITF(P0, sh),     pa1 = BITF(P1, sh);
            uint32_t pa2 = BITF(P0, sh + 4), pa3 = BITF(P1, sh + 4);
            uint32_t na0 = BITF(N0, sh),     na1 = BITF(N1, sh);
            uint32_t na2 = BITF(N0, sh + 4), na3 = BITF(N1, sh + 4);
            const float4* bp = bbase + s * 9 * 32;
            #pragma unroll
            for (int b = 0; b < 9; b++) {
                float4 f = bp[b * 32];
                uint32_t be0 = __float_as_uint(f.x), be1 = __float_as_uint(f.y);
                uint32_t bq0 = __float_as_uint(f.z), bq1 = __float_as_uint(f.w);
                if (b == 8 && g != 0) { be0 = be1 = bq0 = bq1 = 0u; }
                mma8(aP[b], pa0, pa1, pa2, pa3, be0, be1);
                mma8(aN[b], na0, na1, na2, na3, bq0, bq1);
            }
        }
    }

    // ---- epilogue: store fragments to partials ----
    int r0 = strip + wid * 16 + g, r1 = r0 + 8;
    float* p0 = &g_pD[q][r0][0];
    float* p1 = &g_pD[q][r1][0];
    #pragma unroll
    for (int b = 0; b < 8; b++) {
        int col = 8 * b + 2 * c;
        *(float2*)(p0 + col)      = make_float2(aP[b][0], aP[b][1]);
        *(float2*)(p1 + col)      = make_float2(aP[b][2], aP[b][3]);
        *(float2*)(p0 + 64 + col) = make_float2(aN[b][0], aN[b][1]);
        *(float2*)(p1 + 64 + col) = make_float2(aN[b][2], aN[b][3]);
    }
    if (c == 0) {   // den lives in column 0 of nblk 8
        p0[128] = aP[8][0];  p0[129] = aN[8][0];
        p1[128] = aP[8][2];  p1[129] = aN[8][2];
    }
}

// ---------------- kernel 3: combine quarters, divide, ELU ------------------
__global__ void k_final(float* __restrict__ out) {
    int row = blockIdx.x;
    int d = threadIdx.x;                 // 64 threads
    float e1 = g_E1[row], q1 = g_Q1[row];
    float n1 = 0.f, n2 = 0.f, de = 0.f, dq = 0.f;
    #pragma unroll
    for (int q = 0; q < QSPLIT; q++) {
        n1 += g_pD[q][row][d];
        n2 += g_pD[q][row][64 + d];
        de += g_pD[q][row][128];
        dq += g_pD[q][row][129];
    }
    float num = e1 * n1 + q1 * n2;
    float den = e1 * de + q1 * dq;
    float v = num / den;
    out[(size_t)row * OUT_F + d] = (v > 0.f) ? v : expm1f(v);
}

// ---------------- launch ----------------------------------------------------
extern "C" void kernel_launch(void* const* d_in, const int* in_sizes, int n_in,
                              void* d_out, int out_size) {
    const float* X = nullptr; const int* adj = nullptr;
    const float* W = nullptr; const float* a = nullptr;
    for (int i = 0; i < n_in; i++) {
        switch (in_sizes[i]) {
            case N_NODES * IN_F:    X   = (const float*)d_in[i]; break;
            case N_NODES * N_NODES: adj = (const int*)  d_in[i]; break;
            case IN_F * OUT_F:      W   = (const float*)d_in[i]; break;
            case 2 * OUT_F:         a   = (const float*)d_in[i]; break;
        }
    }
    cudaFuncSetAttribute(k_attn, cudaFuncAttributeMaxDynamicSharedMemorySize,
                         SMEM_K2);
    k_h<<<N_NODES / 8, 256>>>(X, W, a);
    dim3 g2(N_NODES / MT, QSPLIT);
    k_attn<<<g2, 256, SMEM_K2>>>(adj);
    k_final<<<N_NODES, OUT_F>>>((float*)d_out);
}